// round 15
// baseline (speedup 1.0000x reference)
#include <cuda_runtime.h>
#include <cuda_bf16.h>

#define S 128
#define NROWS 4096
#define RPB 4                  // rows per block; 2 warps per row (asymmetric)
#define NBLK (NROWS / RPB)     // 1024 blocks, 256 threads

// padded index map: 4 pad floats after every 8 (lane stride 48B -> conflict-free)
#define PADIDX(m) ((m) + 4 * ((m) >> 3))
#define PADLEN 384

__device__ float4 g_part[NBLK];
__device__ unsigned int g_ticket;   // zero at load; reset by last block each run

__device__ __forceinline__ void fma2(unsigned long long& c,
                                     unsigned long long a,
                                     unsigned long long b) {
    asm("fma.rn.f32x2 %0, %1, %2, %0;" : "+l"(c) : "l"(a), "l"(b));
}
__device__ __forceinline__ void add2(unsigned long long& c, unsigned long long a) {
    asm("add.rn.f32x2 %0, %0, %1;" : "+l"(c) : "l"(a));
}
__device__ __forceinline__ float2 unpk(unsigned long long v) {
    float2 r;
    asm("mov.b64 {%0, %1}, %2;" : "=f"(r.x), "=f"(r.y) : "l"(v));
    return r;
}

// One correlation step (zero-copy period-3 ring, identical to R12's mapping):
// loads QX/RX <- orig offs (J+8..J+11) rel. to lane base; T <- t[J..J+3].
#define CITER(J, QX, QY, QZ, RX, RY, RZ)                                     \
    {                                                                        \
        QX = *(const ulonglong2*)(oP  + PADIDX((J) + 8));                    \
        RX = *(const ulonglong2*)(oP1 + PADIDX((J) + 8));                    \
        ulonglong2 T = *(const ulonglong2*)(tb + (J));                       \
        fma2(A0, QX.x, T.x);  /* k=0: off(8,9)   */                          \
        fma2(A1, RZ.y, T.x);  /* k=1: so1(6,7)   */                          \
        fma2(A2, QZ.y, T.x);  /* k=2: off(6,7)   */                          \
        fma2(A3, RZ.x, T.x);  /* k=3: so1(4,5)   */                          \
        fma2(A4, QZ.x, T.x);  /* k=4: off(4,5)   */                          \
        fma2(A5, RY.y, T.x);  /* k=5: so1(2,3)   */                          \
        fma2(A6, QY.y, T.x);  /* k=6: off(2,3)   */                          \
        fma2(A7, RY.x, T.x);  /* k=7: so1(0,1)   */                          \
        fma2(A0, QX.y, T.y);  /* k=0: off(10,11) */                          \
        fma2(A1, RX.x, T.y);  /* k=1: so1(8,9)   */                          \
        fma2(A2, QX.x, T.y);  /* k=2: off(8,9)   */                          \
        fma2(A3, RZ.y, T.y);  /* k=3: so1(6,7)   */                          \
        fma2(A4, QZ.y, T.y);  /* k=4: off(6,7)   */                          \
        fma2(A5, RZ.x, T.y);  /* k=5: so1(4,5)   */                          \
        fma2(A6, QZ.x, T.y);  /* k=6: off(4,5)   */                          \
        fma2(A7, RY.y, T.y);  /* k=7: so1(2,3)   */                          \
    }

__global__ void __launch_bounds__(256, 5) loss3_fused(const float* __restrict__ outp,
                                                      const float* __restrict__ trut,
                                                      float* __restrict__ out) {
    __shared__ float soP[RPB][PADLEN];    // padded o, duplicated (wrap-free)
    __shared__ float so1P[RPB][PADLEN];   // padded o[(i+1) mod 128], duplicated
    __shared__ float stT[RPB][S];         // truth row
    __shared__ float sod[RPB][S];         // plain o row (detail phase)
    __shared__ __align__(16) unsigned long long xacc[RPB][16 * 10]; // sec accums, 80B/lane slot
    __shared__ float4 wres[RPB];
    __shared__ unsigned int sLast;

    const int tid = threadIdx.x;
    const int ww = tid >> 5;
    const int l = tid & 31;
    const int h = l >> 4;          // lane j-half within warp's j-range
    const int p = l & 15;          // lane owns shifts 8p..8p+7
    const bool prim = (ww < 4);
    const int w = prim ? ww : ww - 4;
    const int row = blockIdx.x * RPB + w;

    float ms = 0.f, mo = 0.f, mt = 0.f;

    // ---- primary: load row, build smem images, MSE/max reductions ----
    if (prim) {
        float4 o4 = *(const float4*)(outp + row * S + 4 * l);
        float4 t4 = *(const float4*)(trut + row * S + 4 * l);
        const int ps = PADIDX(4 * l);
        *(float4*)&soP[w][ps]       = o4;
        *(float4*)&soP[w][ps + 192] = o4;           // orig +128 -> padded +192
        *(float4*)&stT[w][4 * l]    = t4;
        *(float4*)&sod[w][4 * l]    = o4;
        float nx = __shfl_sync(0xffffffffu, o4.x, (l + 1) & 31);
        float4 s1 = make_float4(o4.y, o4.z, o4.w, nx);  // o[4l+1..4l+4]
        *(float4*)&so1P[w][ps]       = s1;
        *(float4*)&so1P[w][ps + 192] = s1;

        float d0 = o4.x - t4.x, d1 = o4.y - t4.y, d2 = o4.z - t4.z, d3 = o4.w - t4.w;
        ms = d0 * d0 + d1 * d1 + d2 * d2 + d3 * d3;
        mo = fmaxf(fmaxf(o4.x, o4.y), fmaxf(o4.z, o4.w));
        mt = fmaxf(fmaxf(t4.x, t4.y), fmaxf(t4.z, t4.w));
#pragma unroll
        for (int s = 16; s > 0; s >>= 1) {
            ms += __shfl_xor_sync(0xffffffffu, ms, s);
            mo = fmaxf(mo, __shfl_xor_sync(0xffffffffu, mo, s));
            mt = fmaxf(mt, __shfl_xor_sync(0xffffffffu, mt, s));
        }
    }
    __syncthreads();   // smem images visible to secondary warps

    // ---- correlation: warp pair splits j; lane-halves split again ----
    // primary: j in [0,64); secondary: j in [64,128). Lane base adds 48h+96r.
    const int r = prim ? 0 : 1;
    const float* oP  = &soP[w][12 * (15 - p) + 96 * r + 48 * h];
    const float* oP1 = &so1P[w][12 * (15 - p) + 96 * r + 48 * h];
    const float* tb  = &stT[w][64 * r + 32 * h];

    unsigned long long A0 = 0, A1 = 0, A2 = 0, A3 = 0, A4 = 0, A5 = 0, A6 = 0, A7 = 0;
    ulonglong2 QA, QB, QC, RA, RB, RC;
    QB = *(const ulonglong2*)(oP + PADIDX(0));    // slots (0,1) = offs 0..3
    QC = *(const ulonglong2*)(oP + PADIDX(4));    // slots (2,3) = offs 4..7
    RB = *(const ulonglong2*)(oP1 + PADIDX(0));
    RC = *(const ulonglong2*)(oP1 + PADIDX(4));

    CITER( 0, QA, QB, QC, RA, RB, RC)
    CITER( 4, QB, QC, QA, RB, RC, RA)
    CITER( 8, QC, QA, QB, RC, RA, RB)
    CITER(12, QA, QB, QC, RA, RB, RC)
    CITER(16, QB, QC, QA, RB, RC, RA)
    CITER(20, QC, QA, QB, RC, RA, RB)
    CITER(24, QA, QB, QC, RA, RB, RC)
    CITER(28, QB, QC, QA, RB, RC, RA)

    // ---- combine lane-halves (lanes l and l^16 hold same shifts) ----
    add2(A0, __shfl_xor_sync(0xffffffffu, A0, 16));
    add2(A1, __shfl_xor_sync(0xffffffffu, A1, 16));
    add2(A2, __shfl_xor_sync(0xffffffffu, A2, 16));
    add2(A3, __shfl_xor_sync(0xffffffffu, A3, 16));
    add2(A4, __shfl_xor_sync(0xffffffffu, A4, 16));
    add2(A5, __shfl_xor_sync(0xffffffffu, A5, 16));
    add2(A6, __shfl_xor_sync(0xffffffffu, A6, 16));
    add2(A7, __shfl_xor_sync(0xffffffffu, A7, 16));

    // ---- secondary: publish packed accumulators (stride-80B, conflict-free) ----
    if (!prim && l < 16) {
        unsigned long long* xb = &xacc[w][p * 10];
        ulonglong2 v;
        v.x = A0; v.y = A1; *(ulonglong2*)(xb + 0) = v;
        v.x = A2; v.y = A3; *(ulonglong2*)(xb + 2) = v;
        v.x = A4; v.y = A5; *(ulonglong2*)(xb + 4) = v;
        v.x = A6; v.y = A7; *(ulonglong2*)(xb + 6) = v;
    }
    __syncthreads();   // accumulators visible to primary

    if (prim) {
        // ---- combine with secondary's j-half ----
        const unsigned long long* xb = &xacc[w][p * 10];
        ulonglong2 x01 = *(const ulonglong2*)(xb + 0);
        ulonglong2 x23 = *(const ulonglong2*)(xb + 2);
        ulonglong2 x45 = *(const ulonglong2*)(xb + 4);
        ulonglong2 x67 = *(const ulonglong2*)(xb + 6);
        add2(A0, x01.x); add2(A1, x01.y);
        add2(A2, x23.x); add2(A3, x23.y);
        add2(A4, x45.x); add2(A5, x45.y);
        add2(A6, x67.x); add2(A7, x67.y);
        float2 c0 = unpk(A0), c1 = unpk(A1), c2 = unpk(A2), c3 = unpk(A3);
        float2 c4 = unpk(A4), c5 = unpk(A5), c6 = unpk(A6), c7 = unpk(A7);
        float v0 = c0.x + c0.y, v1 = c1.x + c1.y, v2 = c2.x + c2.y, v3 = c3.x + c3.y;
        float v4 = c4.x + c4.y, v5 = c5.x + c5.y, v6 = c6.x + c6.y, v7 = c7.x + c7.y;

        // ---- argmax corr == argmin shiftDiff; tie-break -> smaller shift ----
        float bc = v0; int bs = 8 * p;
        if (v1 > bc) { bc = v1; bs = 8 * p + 1; }
        if (v2 > bc) { bc = v2; bs = 8 * p + 2; }
        if (v3 > bc) { bc = v3; bs = 8 * p + 3; }
        if (v4 > bc) { bc = v4; bs = 8 * p + 4; }
        if (v5 > bc) { bc = v5; bs = 8 * p + 5; }
        if (v6 > bc) { bc = v6; bs = 8 * p + 6; }
        if (v7 > bc) { bc = v7; bs = 8 * p + 7; }
#pragma unroll
        for (int s = 8; s > 0; s >>= 1) {   // halves identical -> width-16 reduce
            float oc = __shfl_xor_sync(0xffffffffu, bc, s);
            int   os = __shfl_xor_sync(0xffffffffu, bs, s);
            if (oc > bc || (oc == bc && os < bs)) { bc = oc; bs = os; }
        }
        const int b = bs;                  // all lanes agree
        const float scale = mt / mo;       // max(rolled) == max(output)

        // ---- detail loss: g = cgrad(rolled*scale - truth), cgrad linear ----
        float4 t4d = *(const float4*)&stT[w][4 * l];   // reload (short live range)
        float dd0 = sod[w][(4 * l     - b) & 127] * scale - t4d.x;
        float dd1 = sod[w][(4 * l + 1 - b) & 127] * scale - t4d.y;
        float dd2 = sod[w][(4 * l + 2 - b) & 127] * scale - t4d.z;
        float dd3 = sod[w][(4 * l + 3 - b) & 127] * scale - t4d.w;
        float dm = __shfl_sync(0xffffffffu, dd3, (l + 31) & 31);  // d[4l-1] circ
        float dp = __shfl_sync(0xffffffffu, dd0, (l + 1) & 31);   // d[4l+4] circ
        float g0 = dd0 - 0.5f * (dm  + dd1);
        float g1 = dd1 - 0.5f * (dd0 + dd2);
        float g2 = dd2 - 0.5f * (dd1 + dd3);
        float g3 = dd3 - 0.5f * (dd2 + dp);
        float gg = fmaf(g0, g0, fmaf(g1, g1, fmaf(g2, g2, g3 * g3)));
#pragma unroll
        for (int s = 16; s > 0; s >>= 1) gg += __shfl_xor_sync(0xffffffffu, gg, s);

        if (l == 0) wres[w] = make_float4((float)b, fabsf(scale - 1.0f), sqrtf(gg), ms);
    }
    __syncthreads();

    // ---- per-block partial (fixed order), ticket ----
    if (tid == 0) {
        float4 rr = wres[0];
#pragma unroll
        for (int k = 1; k < RPB; k++) {
            float4 q = wres[k];
            rr.x += q.x; rr.y += q.y; rr.z += q.z; rr.w += q.w;
        }
        g_part[blockIdx.x] = rr;
        __threadfence();
        unsigned int old = atomicAdd(&g_ticket, 1u);
        sLast = (old == NBLK - 1) ? 1u : 0u;
    }
    __syncthreads();

    // ---- last block finalizes (deterministic fixed-order reduction) ----
    if (sLast) {
        float fa = 0.f, fb = 0.f, fc = 0.f, fd = 0.f;
#pragma unroll
        for (int i = tid; i < NBLK; i += 256) {
            float4 q = g_part[i];
            fa += q.x; fb += q.y; fc += q.z; fd += q.w;
        }
        float4* fr = (float4*)&soP[0][0];   // 256*16B = 4KB <= sizeof(soP)
        fr[tid] = make_float4(fa, fb, fc, fd);
        __syncthreads();
#pragma unroll
        for (int stp = 128; stp > 0; stp >>= 1) {
            if (tid < stp) {
                float4 x = fr[tid], y = fr[tid + stp];
                fr[tid] = make_float4(x.x + y.x, x.y + y.y, x.z + y.z, x.w + y.w);
            }
            __syncthreads();
        }
        if (tid == 0) {
            float4 rr = fr[0];
            out[0] = 50.0f * rr.x + 100.0f * rr.y + 0.1f * rr.z + sqrtf(rr.w);
            g_ticket = 0u;   // reset for next graph replay
        }
    }
}

extern "C" void kernel_launch(void* const* d_in, const int* in_sizes, int n_in,
                              void* d_out, int out_size) {
    (void)n_in; (void)out_size; (void)in_sizes;
    const float* outp = (const float*)d_in[0];
    const float* trut = (const float*)d_in[1];
    float* res = (float*)d_out;
    loss3_fused<<<NBLK, 256>>>(outp, trut, res);
}

// round 16
// speedup vs baseline: 1.1373x; 1.1373x over previous
#include <cuda_runtime.h>
#include <cuda_bf16.h>

#define S 128
#define NROWS 4096
#define WPB 4                 // warps per block; 1 row-pair per warp
#define RPB 8                 // rows per block
#define NBLK (NROWS / RPB)    // 512 blocks

// u64-index pad: 2 pad u64s after every 4 -> lane stride 48B, conflict-free
#define PADU(m) ((m) + 2 * ((m) >> 2))
#define PADULEN 384           // covers u64 indices [0,256)

__device__ float4 g_part[NBLK];
__device__ unsigned int g_ticket;   // zero at load; reset by last block each run

__device__ __forceinline__ void fma2(unsigned long long& c,
                                     unsigned long long a,
                                     unsigned long long b) {
    asm("fma.rn.f32x2 %0, %1, %2, %0;" : "+l"(c) : "l"(a), "l"(b));
}
__device__ __forceinline__ float2 unpk(unsigned long long v) {
    float2 r;
    asm("mov.b64 {%0, %1}, %2;" : "=f"(r.x), "=f"(r.y) : "l"(v));
    return r;
}

// One step (4 j's, 4 shifts, BOTH rows). Window W0..W3 = u64 slots
// (J,J+1),(J+2,J+3),(J+4,J+5),(J+6,J+7); loads W2,W3; j-ascending per acc.
// slot(j,k) = b0 + J + dj + 4 - k; padded offsets PADU(J)+{6,8} compile-time.
#define CITER2(J, W0, W1, W2, W3)                                          \
    {                                                                      \
        W2 = *(const ulonglong2*)(oB8 + PADU(J) + 6);                      \
        W3 = *(const ulonglong2*)(oB8 + PADU(J) + 8);                      \
        ulonglong2 T0 = *(const ulonglong2*)(tB8 + (J));                   \
        ulonglong2 T1 = *(const ulonglong2*)(tB8 + (J) + 2);               \
        fma2(A0, W2.x, T0.x);  /* k=0, j=J   */                            \
        fma2(A1, W1.y, T0.x);                                              \
        fma2(A2, W1.x, T0.x);                                              \
        fma2(A3, W0.y, T0.x);                                              \
        fma2(A0, W2.y, T0.y);  /* j=J+1 */                                 \
        fma2(A1, W2.x, T0.y);                                              \
        fma2(A2, W1.y, T0.y);                                              \
        fma2(A3, W1.x, T0.y);                                              \
        fma2(A0, W3.x, T1.x);  /* j=J+2 */                                 \
        fma2(A1, W2.y, T1.x);                                              \
        fma2(A2, W2.x, T1.x);                                              \
        fma2(A3, W1.y, T1.x);                                              \
        fma2(A0, W3.y, T1.y);  /* j=J+3 */                                 \
        fma2(A1, W3.x, T1.y);                                              \
        fma2(A2, W2.y, T1.y);                                              \
        fma2(A3, W2.x, T1.y);                                              \
    }

__global__ void __launch_bounds__(128) loss3_fused(const float* __restrict__ outp,
                                                   const float* __restrict__ trut,
                                                   float* __restrict__ out) {
    __shared__ __align__(16) unsigned long long oAB[WPB][PADULEN]; // (oA,oB) padded, dup
    __shared__ __align__(16) unsigned long long tAB[WPB][S];       // (tA,tB)
    __shared__ float4 wres[RPB];
    __shared__ unsigned int sLast;

    const int tid = threadIdx.x;
    const int w = tid >> 5;       // warp = row pair
    const int l = tid & 31;       // lane owns shifts 4l..4l+3 (both rows)
    const int rowA = blockIdx.x * RPB + 2 * w;
    const int rowB = rowA + 1;

    // ---- load both rows, build interleaved padded images ----
    float4 oA = *(const float4*)(outp + rowA * S + 4 * l);
    float4 tA = *(const float4*)(trut + rowA * S + 4 * l);
    float4 oB = *(const float4*)(outp + rowB * S + 4 * l);
    float4 tB = *(const float4*)(trut + rowB * S + 4 * l);
    float* oABf = (float*)&oAB[w][0];
    float* tABf = (float*)&tAB[w][0];
    // u64 elem i=(oA[i],oB[i]); float4 covers u64 pair. PADU(4l)=6l.
    *(float4*)&oABf[12 * l]           = make_float4(oA.x, oB.x, oA.y, oB.y);
    *(float4*)&oABf[12 * l + 4]       = make_float4(oA.z, oB.z, oA.w, oB.w);
    *(float4*)&oABf[12 * l + 384]     = make_float4(oA.x, oB.x, oA.y, oB.y); // dup +192 u64
    *(float4*)&oABf[12 * l + 388]     = make_float4(oA.z, oB.z, oA.w, oB.w);
    *(float4*)&tABf[8 * l]            = make_float4(tA.x, tB.x, tA.y, tB.y);
    *(float4*)&tABf[8 * l + 4]        = make_float4(tA.z, tB.z, tA.w, tB.w);
    __syncwarp();

    // ---- per-row MSE, max(o), max(t): interleaved shuffle chains ----
    float dAx = oA.x - tA.x, dAy = oA.y - tA.y, dAz = oA.z - tA.z, dAw = oA.w - tA.w;
    float dBx = oB.x - tB.x, dBy = oB.y - tB.y, dBz = oB.z - tB.z, dBw = oB.w - tB.w;
    float msA = dAx * dAx + dAy * dAy + dAz * dAz + dAw * dAw;
    float msB = dBx * dBx + dBy * dBy + dBz * dBz + dBw * dBw;
    float moA = fmaxf(fmaxf(oA.x, oA.y), fmaxf(oA.z, oA.w));
    float moB = fmaxf(fmaxf(oB.x, oB.y), fmaxf(oB.z, oB.w));
    float mtA = fmaxf(fmaxf(tA.x, tA.y), fmaxf(tA.z, tA.w));
    float mtB = fmaxf(fmaxf(tB.x, tB.y), fmaxf(tB.z, tB.w));
#pragma unroll
    for (int s = 16; s > 0; s >>= 1) {
        msA += __shfl_xor_sync(0xffffffffu, msA, s);
        msB += __shfl_xor_sync(0xffffffffu, msB, s);
        moA = fmaxf(moA, __shfl_xor_sync(0xffffffffu, moA, s));
        moB = fmaxf(moB, __shfl_xor_sync(0xffffffffu, moB, s));
        mtA = fmaxf(mtA, __shfl_xor_sync(0xffffffffu, mtA, s));
        mtB = fmaxf(mtB, __shfl_xor_sync(0xffffffffu, mtB, s));
    }

    // ---- packed circular correlation: acc k = (corrA, corrB) of shift 4l+k ----
    // dup index = j - s + 128 = b0 + J + dj + 4 - k, b0 = 124 - 4l (mult of 4).
    // padded lane base = PADU(124-4l) = 186 - 6l.
    const unsigned long long* oB8 = &oAB[w][186 - 6 * l];
    const unsigned long long* tB8 = &tAB[w][0];

    unsigned long long A0 = 0, A1 = 0, A2 = 0, A3 = 0;
    ulonglong2 WA, WB, WC, WD;
    WA = *(const ulonglong2*)(oB8);        // slots (0,1)
    WB = *(const ulonglong2*)(oB8 + 2);    // slots (2,3)

    CITER2(  0, WA, WB, WC, WD)
    CITER2(  4, WC, WD, WA, WB)
    CITER2(  8, WA, WB, WC, WD)
    CITER2( 12, WC, WD, WA, WB)
    CITER2( 16, WA, WB, WC, WD)
    CITER2( 20, WC, WD, WA, WB)
    CITER2( 24, WA, WB, WC, WD)
    CITER2( 28, WC, WD, WA, WB)
    CITER2( 32, WA, WB, WC, WD)
    CITER2( 36, WC, WD, WA, WB)
    CITER2( 40, WA, WB, WC, WD)
    CITER2( 44, WC, WD, WA, WB)
    CITER2( 48, WA, WB, WC, WD)
    CITER2( 52, WC, WD, WA, WB)
    CITER2( 56, WA, WB, WC, WD)
    CITER2( 60, WC, WD, WA, WB)
    CITER2( 64, WA, WB, WC, WD)
    CITER2( 68, WC, WD, WA, WB)
    CITER2( 72, WA, WB, WC, WD)
    CITER2( 76, WC, WD, WA, WB)
    CITER2( 80, WA, WB, WC, WD)
    CITER2( 84, WC, WD, WA, WB)
    CITER2( 88, WA, WB, WC, WD)
    CITER2( 92, WC, WD, WA, WB)
    CITER2( 96, WA, WB, WC, WD)
    CITER2(100, WC, WD, WA, WB)
    CITER2(104, WA, WB, WC, WD)
    CITER2(108, WC, WD, WA, WB)
    CITER2(112, WA, WB, WC, WD)
    CITER2(116, WC, WD, WA, WB)
    CITER2(120, WA, WB, WC, WD)
    CITER2(124, WC, WD, WA, WB)

    float2 c0 = unpk(A0), c1 = unpk(A1), c2 = unpk(A2), c3 = unpk(A3);

    // ---- argmax per row (tie -> smaller shift), dual interleaved chains ----
    float bcA = c0.x; int bsA = 4 * l;
    float bcB = c0.y; int bsB = 4 * l;
    if (c1.x > bcA) { bcA = c1.x; bsA = 4 * l + 1; }
    if (c1.y > bcB) { bcB = c1.y; bsB = 4 * l + 1; }
    if (c2.x > bcA) { bcA = c2.x; bsA = 4 * l + 2; }
    if (c2.y > bcB) { bcB = c2.y; bsB = 4 * l + 2; }
    if (c3.x > bcA) { bcA = c3.x; bsA = 4 * l + 3; }
    if (c3.y > bcB) { bcB = c3.y; bsB = 4 * l + 3; }
#pragma unroll
    for (int s = 16; s > 0; s >>= 1) {
        float ocA = __shfl_xor_sync(0xffffffffu, bcA, s);
        int   osA = __shfl_xor_sync(0xffffffffu, bsA, s);
        float ocB = __shfl_xor_sync(0xffffffffu, bcB, s);
        int   osB = __shfl_xor_sync(0xffffffffu, bsB, s);
        if (ocA > bcA || (ocA == bcA && osA < bsA)) { bcA = ocA; bsA = osA; }
        if (ocB > bcB || (ocB == bcB && osB < bsB)) { bcB = ocB; bsB = osB; }
    }
    const int bA = bsA, bB = bsB;
    const float scaleA = mtA / moA;   // max(rolled) == max(output)
    const float scaleB = mtB / moB;

    // ---- detail loss both rows: d[i] = o[(i-b)&127]*scale - t[i] ----
    // dup index m = i - b + 128 in [1,255]; float idx = 2*PADU(m) + rowpar.
    float dA0, dA1, dA2, dA3, dB0, dB1, dB2, dB3;
    {
        int mA = 4 * l - bA + 128, mB = 4 * l - bB + 128;
        dA0 = oABf[2 * PADU(mA)     ] * scaleA - tA.x;
        dB0 = oABf[2 * PADU(mB) + 1 ] * scaleB - tB.x;
        dA1 = oABf[2 * PADU(mA + 1) ] * scaleA - tA.y;
        dB1 = oABf[2 * PADU(mB + 1) + 1] * scaleB - tB.y;
        dA2 = oABf[2 * PADU(mA + 2) ] * scaleA - tA.z;
        dB2 = oABf[2 * PADU(mB + 2) + 1] * scaleB - tB.z;
        dA3 = oABf[2 * PADU(mA + 3) ] * scaleA - tA.w;
        dB3 = oABf[2 * PADU(mB + 3) + 1] * scaleB - tB.w;
    }
    float dmA = __shfl_sync(0xffffffffu, dA3, (l + 31) & 31);
    float dpA = __shfl_sync(0xffffffffu, dA0, (l + 1) & 31);
    float dmB = __shfl_sync(0xffffffffu, dB3, (l + 31) & 31);
    float dpB = __shfl_sync(0xffffffffu, dB0, (l + 1) & 31);
    float gA0 = dA0 - 0.5f * (dmA + dA1);
    float gA1 = dA1 - 0.5f * (dA0 + dA2);
    float gA2 = dA2 - 0.5f * (dA1 + dA3);
    float gA3 = dA3 - 0.5f * (dA2 + dpA);
    float gB0 = dB0 - 0.5f * (dmB + dB1);
    float gB1 = dB1 - 0.5f * (dB0 + dB2);
    float gB2 = dB2 - 0.5f * (dB1 + dB3);
    float gB3 = dB3 - 0.5f * (dB2 + dpB);
    float ggA = fmaf(gA0, gA0, fmaf(gA1, gA1, fmaf(gA2, gA2, gA3 * gA3)));
    float ggB = fmaf(gB0, gB0, fmaf(gB1, gB1, fmaf(gB2, gB2, gB3 * gB3)));
#pragma unroll
    for (int s = 16; s > 0; s >>= 1) {
        ggA += __shfl_xor_sync(0xffffffffu, ggA, s);
        ggB += __shfl_xor_sync(0xffffffffu, ggB, s);
    }

    // ---- per-block partial (fixed order over 8 rows) ----
    if (l == 0) {
        wres[2 * w]     = make_float4((float)bA, fabsf(scaleA - 1.0f), sqrtf(ggA), msA);
        wres[2 * w + 1] = make_float4((float)bB, fabsf(scaleB - 1.0f), sqrtf(ggB), msB);
    }
    __syncthreads();
    if (tid == 0) {
        float4 r = wres[0];
#pragma unroll
        for (int k = 1; k < RPB; k++) {
            float4 q = wres[k];
            r.x += q.x; r.y += q.y; r.z += q.z; r.w += q.w;
        }
        g_part[blockIdx.x] = r;
        __threadfence();
        unsigned int old = atomicAdd(&g_ticket, 1u);
        sLast = (old == NBLK - 1) ? 1u : 0u;
    }
    __syncthreads();

    // ---- last block finalizes (deterministic fixed-order reduction) ----
    if (sLast) {
        float fa = 0.f, fb = 0.f, fc = 0.f, fd = 0.f;
#pragma unroll
        for (int i = tid; i < NBLK; i += 128) {
            float4 q = g_part[i];
            fa += q.x; fb += q.y; fc += q.z; fd += q.w;
        }
        float4* fr = (float4*)&oAB[0][0];   // reuse smem (2KB of 12KB)
        fr[tid] = make_float4(fa, fb, fc, fd);
        __syncthreads();
#pragma unroll
        for (int stp = 64; stp > 0; stp >>= 1) {
            if (tid < stp) {
                float4 x = fr[tid], y = fr[tid + stp];
                fr[tid] = make_float4(x.x + y.x, x.y + y.y, x.z + y.z, x.w + y.w);
            }
            __syncthreads();
        }
        if (tid == 0) {
            float4 r = fr[0];
            out[0] = 50.0f * r.x + 100.0f * r.y + 0.1f * r.z + sqrtf(r.w);
            g_ticket = 0u;   // reset for next graph replay
        }
    }
}

extern "C" void kernel_launch(void* const* d_in, const int* in_sizes, int n_in,
                              void* d_out, int out_size) {
    (void)n_in; (void)out_size; (void)in_sizes;
    const float* outp = (const float*)d_in[0];
    const float* trut = (const float*)d_in[1];
    float* res = (float*)d_out;
    loss3_fused<<<NBLK, 128>>>(outp, trut, res);
}

// round 17
// speedup vs baseline: 1.3892x; 1.2216x over previous
#include <cuda_runtime.h>
#include <cuda_bf16.h>

#define S 128
#define NROWS 4096
#define RPB 4                 // rows per block (one warp per row)
#define NBLK (NROWS / RPB)    // 1024 blocks

__device__ float4 g_part[NBLK];
__device__ unsigned int g_ticket;   // zero at load; reset by last block each run

// One correlation step (scalar FFMA, zero-copy period-2 float4 ring).
// ob[i] = so2[w][124-4l + i]; obl[i] = so1[...] = ob[i+1]; tb = truth.
// acc_k needs o-dup idx (J+dj+4-k):
//   k=0: U.x..U.w          (U  = ob[J+4..J+7])
//   k=2: Up.z,Up.w,U.x,U.y (Up = ob[J..J+3])
//   k=1: Vp.z,Vp.w,V.x,V.y (V  = obl[J+4..J+7] = o[J+5..J+8])
//   k=3: Vp.x..Vp.w
#define SITER(J, U, Up, V, Vp)                                             \
    {                                                                      \
        U = *(const float4*)(ob + (J) + 4);                                \
        V = *(const float4*)(obl + (J) + 4);                               \
        float4 T = *(const float4*)(tb + (J));                             \
        acc0 = fmaf(U.x,  T.x, acc0);                                      \
        acc1 = fmaf(Vp.z, T.x, acc1);                                      \
        acc2 = fmaf(Up.z, T.x, acc2);                                      \
        acc3 = fmaf(Vp.x, T.x, acc3);                                      \
        acc0 = fmaf(U.y,  T.y, acc0);                                      \
        acc1 = fmaf(Vp.w, T.y, acc1);                                      \
        acc2 = fmaf(Up.w, T.y, acc2);                                      \
        acc3 = fmaf(Vp.y, T.y, acc3);                                      \
        acc0 = fmaf(U.z,  T.z, acc0);                                      \
        acc1 = fmaf(V.x,  T.z, acc1);                                      \
        acc2 = fmaf(U.x,  T.z, acc2);                                      \
        acc3 = fmaf(Vp.z, T.z, acc3);                                      \
        acc0 = fmaf(U.w,  T.w, acc0);                                      \
        acc1 = fmaf(V.y,  T.w, acc1);                                      \
        acc2 = fmaf(U.y,  T.w, acc2);                                      \
        acc3 = fmaf(Vp.w, T.w, acc3);                                      \
    }

__global__ void __launch_bounds__(128) loss3_fused(const float* __restrict__ outp,
                                                   const float* __restrict__ trut,
                                                   float* __restrict__ out) {
    __shared__ float so2[RPB][2 * S];   // output row, duplicated (wrap-free)
    __shared__ float so1[RPB][2 * S];   // so1[i] = o[(i+1) mod 128], duplicated
    __shared__ float stT[RPB][S];       // truth row
    __shared__ float4 wres[RPB];
    __shared__ unsigned int sLast;

    const int tid = threadIdx.x;
    const int w = tid >> 5;     // warp = row within block
    const int l = tid & 31;     // lane owns shifts 4l..4l+3
    const int row = blockIdx.x * RPB + w;

    // ---- load row (coalesced float4), mirror into smem ----
    float4 o4 = *(const float4*)(outp + row * S + 4 * l);
    float4 t4 = *(const float4*)(trut + row * S + 4 * l);
    *(float4*)&so2[w][4 * l]     = o4;
    *(float4*)&so2[w][S + 4 * l] = o4;
    *(float4*)&stT[w][4 * l]     = t4;
    // shifted copy: so1[4l..4l+3] = o[4l+1..4l+4]
    float nx = __shfl_sync(0xffffffffu, o4.x, (l + 1) & 31);
    float4 s1 = make_float4(o4.y, o4.z, o4.w, nx);
    *(float4*)&so1[w][4 * l]     = s1;
    *(float4*)&so1[w][S + 4 * l] = s1;
    __syncwarp();

    // ---- row MSE, max(output), max(truth): warp shuffles ----
    float d0 = o4.x - t4.x, d1 = o4.y - t4.y, d2 = o4.z - t4.z, d3 = o4.w - t4.w;
    float ms = d0 * d0 + d1 * d1 + d2 * d2 + d3 * d3;
    float mo = fmaxf(fmaxf(o4.x, o4.y), fmaxf(o4.z, o4.w));
    float mt = fmaxf(fmaxf(t4.x, t4.y), fmaxf(t4.z, t4.w));
#pragma unroll
    for (int s = 16; s > 0; s >>= 1) {
        ms += __shfl_xor_sync(0xffffffffu, ms, s);
        mo = fmaxf(mo, __shfl_xor_sync(0xffffffffu, mo, s));
        mt = fmaxf(mt, __shfl_xor_sync(0xffffffffu, mt, s));
    }

    // ---- circular correlation, scalar FFMA, 3 LDS.128 / 16 FFMA per step ----
    const float* ob  = &so2[w][124 - 4 * l];   // 16B-aligned, conflict-free stride
    const float* obl = &so1[w][124 - 4 * l];
    const float* tb  = &stT[w][0];
    float acc0 = 0.f, acc1 = 0.f, acc2 = 0.f, acc3 = 0.f;
    float4 UX, UY, VX, VY;
    UY = *(const float4*)(ob);     // offs 0..3
    VY = *(const float4*)(obl);

    SITER( 0, UX, UY, VX, VY)
    SITER( 4, UY, UX, VY, VX)
    SITER( 8, UX, UY, VX, VY)
    SITER(12, UY, UX, VY, VX)
    SITER(16, UX, UY, VX, VY)
    SITER(20, UY, UX, VY, VX)
    SITER(24, UX, UY, VX, VY)
    SITER(28, UY, UX, VY, VX)
    SITER(32, UX, UY, VX, VY)
    SITER(36, UY, UX, VY, VX)
    SITER(40, UX, UY, VX, VY)
    SITER(44, UY, UX, VY, VX)
    SITER(48, UX, UY, VX, VY)
    SITER(52, UY, UX, VY, VX)
    SITER(56, UX, UY, VX, VY)
    SITER(60, UY, UX, VY, VX)

    // ---- argmax corr == argmin shiftDiff; tie-break -> smaller shift ----
    float bc = acc0; int bs = 4 * l;
    if (acc1 > bc) { bc = acc1; bs = 4 * l + 1; }
    if (acc2 > bc) { bc = acc2; bs = 4 * l + 2; }
    if (acc3 > bc) { bc = acc3; bs = 4 * l + 3; }
#pragma unroll
    for (int s = 16; s > 0; s >>= 1) {
        float oc = __shfl_xor_sync(0xffffffffu, bc, s);
        int   os = __shfl_xor_sync(0xffffffffu, bs, s);
        if (oc > bc || (oc == bc && os < bs)) { bc = oc; bs = os; }
    }
    const int b = bs;
    const float scale = mt / mo;   // max(rolled) == max(output): roll is a permutation

    // ---- detail loss: g = cgrad(rolled*scale - truth), cgrad linear ----
    float dd0 = so2[w][(4 * l     - b) & 127] * scale - t4.x;
    float dd1 = so2[w][(4 * l + 1 - b) & 127] * scale - t4.y;
    float dd2 = so2[w][(4 * l + 2 - b) & 127] * scale - t4.z;
    float dd3 = so2[w][(4 * l + 3 - b) & 127] * scale - t4.w;
    float dm = __shfl_sync(0xffffffffu, dd3, (l + 31) & 31);  // d[4l-1] circular
    float dp = __shfl_sync(0xffffffffu, dd0, (l + 1) & 31);   // d[4l+4] circular
    float g0 = dd0 - 0.5f * (dm  + dd1);
    float g1 = dd1 - 0.5f * (dd0 + dd2);
    float g2 = dd2 - 0.5f * (dd1 + dd3);
    float g3 = dd3 - 0.5f * (dd2 + dp);
    float gg = fmaf(g0, g0, fmaf(g1, g1, fmaf(g2, g2, g3 * g3)));
#pragma unroll
    for (int s = 16; s > 0; s >>= 1) gg += __shfl_xor_sync(0xffffffffu, gg, s);

    // ---- per-block partial (fixed order: warp 0..3) ----
    if (l == 0) wres[w] = make_float4((float)b, fabsf(scale - 1.0f), sqrtf(gg), ms);
    __syncthreads();
    if (tid == 0) {
        float4 r = wres[0];
#pragma unroll
        for (int k = 1; k < RPB; k++) {
            float4 q = wres[k];
            r.x += q.x; r.y += q.y; r.z += q.z; r.w += q.w;
        }
        g_part[blockIdx.x] = r;
        __threadfence();
        unsigned int old = atomicAdd(&g_ticket, 1u);
        sLast = (old == NBLK - 1) ? 1u : 0u;
    }
    __syncthreads();

    // ---- last block finalizes (deterministic fixed-order reduction) ----
    if (sLast) {
        float a = 0.f, bb = 0.f, c = 0.f, dd = 0.f;
#pragma unroll
        for (int i = tid; i < NBLK; i += 128) {
            float4 q = g_part[i];
            a += q.x; bb += q.y; c += q.z; dd += q.w;
        }
        float4* fr = (float4*)&so2[0][0];   // reuse smem
        fr[tid] = make_float4(a, bb, c, dd);
        __syncthreads();
#pragma unroll
        for (int stp = 64; stp > 0; stp >>= 1) {
            if (tid < stp) {
                float4 x = fr[tid], y = fr[tid + stp];
                fr[tid] = make_float4(x.x + y.x, x.y + y.y, x.z + y.z, x.w + y.w);
            }
            __syncthreads();
        }
        if (tid == 0) {
            float4 r = fr[0];
            out[0] = 50.0f * r.x + 100.0f * r.y + 0.1f * r.z + sqrtf(r.w);
            g_ticket = 0u;   // reset for next graph replay
        }
    }
}

extern "C" void kernel_launch(void* const* d_in, const int* in_sizes, int n_in,
                              void* d_out, int out_size) {
    (void)n_in; (void)out_size; (void)in_sizes;
    const float* outp = (const float*)d_in[0];
    const float* trut = (const float*)d_in[1];
    float* res = (float*)d_out;
    loss3_fused<<<NBLK, 128>>>(outp, trut, res);
}